// round 4
// baseline (speedup 1.0000x reference)
#include <cuda_runtime.h>
#include <math.h>
#include <float.h>
#include <stdint.h>

// ---------------------------------------------------------------------------
// PointEncoder: FF1 -> FF2 -> 4x attention -> concat -> FF_final
// N=8192, D=512, MD=128, OUT_F=1024. TF32 tensor cores + fused flash attention.
// ---------------------------------------------------------------------------

#define NROWS 8192
#define DMODEL 512
#define MDIM 128
#define OUTF 1024

// Static scratch
__device__ float g_h[NROWS * DMODEL];
__device__ float g_tmp[NROWS * DMODEL];
__device__ float g_QKV[NROWS * 768];           // Q|K|V concat per row
__device__ float g_AV[NROWS * DMODEL];
__device__ float g_cat[NROWS * 4 * DMODEL];
// tf32-rounded weights
__device__ float g_W2r[DMODEL * DMODEL];
__device__ float g_Wqkv[DMODEL * 768];         // WQ|WK|WV concat, tf32
__device__ float g_WOr[DMODEL * DMODEL];
__device__ float g_Wfr[4 * DMODEL * OUTF];

__device__ __forceinline__ float to_tf32(float x) {
    uint32_t r;
    asm("cvt.rna.tf32.f32 %0, %1;" : "=r"(r) : "f"(x));
    return __uint_as_float(r);
}

// ---------------------------------------------------------------------------
// Reductions
// ---------------------------------------------------------------------------
__device__ __forceinline__ float warpReduceSum(float v) {
#pragma unroll
    for (int o = 16; o > 0; o >>= 1) v += __shfl_xor_sync(0xffffffff, v, o);
    return v;
}
__device__ float blockReduceSum(float v) {
    __shared__ float sh[32];
    __shared__ float res;
    int lane = threadIdx.x & 31, wid = threadIdx.x >> 5;
    v = warpReduceSum(v);
    if (lane == 0) sh[wid] = v;
    __syncthreads();
    int nw = (blockDim.x + 31) >> 5;
    float t = (threadIdx.x < nw) ? sh[threadIdx.x] : 0.0f;
    if (wid == 0) { t = warpReduceSum(t); if (lane == 0) res = t; }
    __syncthreads();
    return res;
}

// ---------------------------------------------------------------------------
// cp.async helpers
// ---------------------------------------------------------------------------
__device__ __forceinline__ void cp16(float* dst, const float* src) {
    uint32_t d = (uint32_t)__cvta_generic_to_shared(dst);
    asm volatile("cp.async.cg.shared.global [%0], [%1], 16;\n" :: "r"(d), "l"(src));
}
__device__ __forceinline__ void cp_commit() { asm volatile("cp.async.commit_group;\n"); }
__device__ __forceinline__ void cp_wait1() { asm volatile("cp.async.wait_group 1;\n"); }
__device__ __forceinline__ void cp_wait0() { asm volatile("cp.async.wait_group 0;\n"); }

// ---------------------------------------------------------------------------
// TF32 GEMM (from R3): C = alpha * A @ op(B) + bias
// ---------------------------------------------------------------------------
#define GBM 128
#define GBN 128
#define GBK 32

template <bool BT>
__global__ void __launch_bounds__(256, 2) gemm_tf32(
    int M, int N, int K,
    const float* __restrict__ A, int lda,
    const float* __restrict__ B, int ldb,
    float* __restrict__ C, int ldc,
    const float* __restrict__ bias, float alpha, int roundOut)
{
    constexpr int ASZ = 128 * 36;
    constexpr int BSZ = BT ? 128 * 36 : 32 * 136;
    extern __shared__ float sm[];

    const int t    = threadIdx.x;
    const int wid  = t >> 5;
    const int lane = t & 31;
    const int g    = lane >> 2;
    const int t4   = lane & 3;
    const int wm   = wid & 1;
    const int wn   = wid >> 1;
    const int bx   = blockIdx.x;
    const int by   = blockIdx.y;

    const float* Ab = A + (size_t)by * GBM * lda;
    const float* Bb = BT ? (B + (size_t)bx * GBN * ldb) : (B + bx * GBN);

    const int ar  = t >> 3;
    const int ac  = (t & 7) * 4;
    const int br  = t >> 5;
    const int bc4 = (t & 31) * 4;

    float acc[4][4][4];
#pragma unroll
    for (int mt = 0; mt < 4; mt++)
#pragma unroll
        for (int nt = 0; nt < 4; nt++)
#pragma unroll
            for (int r = 0; r < 4; r++) acc[mt][nt][r] = 0.0f;

    const int tiles = K / GBK;

    auto load_tile = [&](int stage, int k0) {
        float* as = sm + stage * ASZ;
        float* bs = sm + 2 * ASZ + stage * BSZ;
#pragma unroll
        for (int i = 0; i < 4; i++) {
            int row = ar + 32 * i;
            cp16(as + row * 36 + ac, Ab + (size_t)row * lda + k0 + ac);
        }
        if (BT) {
#pragma unroll
            for (int i = 0; i < 4; i++) {
                int row = ar + 32 * i;
                cp16(bs + row * 36 + ac, Bb + (size_t)row * ldb + k0 + ac);
            }
        } else {
#pragma unroll
            for (int i = 0; i < 4; i++) {
                int r = br + 8 * i;
                cp16(bs + r * 136 + bc4, Bb + (size_t)(k0 + r) * ldb + bc4);
            }
        }
        cp_commit();
    };

    load_tile(0, 0);

    for (int tt = 0; tt < tiles; tt++) {
        if (tt + 1 < tiles) {
            load_tile((tt + 1) & 1, (tt + 1) * GBK);
            cp_wait1();
        } else {
            cp_wait0();
        }
        __syncthreads();

        const int stage = tt & 1;
        const float* as = sm + stage * ASZ;
        const float* bs = sm + 2 * ASZ + stage * BSZ;
        const uint32_t* ap = (const uint32_t*)(as + (wm * 64 + g) * 36 + t4);
        const uint32_t* bp = BT ? (const uint32_t*)(bs + (wn * 32 + g) * 36 + t4)
                                : (const uint32_t*)(bs + t4 * 136 + wn * 32 + g);

#pragma unroll
        for (int k8 = 0; k8 < 4; k8++) {
            uint32_t a[4][4];
#pragma unroll
            for (int mt = 0; mt < 4; mt++) {
                a[mt][0] = ap[mt * 576 + k8 * 8];
                a[mt][1] = ap[mt * 576 + 288 + k8 * 8];
                a[mt][2] = ap[mt * 576 + k8 * 8 + 4];
                a[mt][3] = ap[mt * 576 + 288 + k8 * 8 + 4];
            }
            uint32_t b[4][2];
#pragma unroll
            for (int nt = 0; nt < 4; nt++) {
                if (BT) {
                    b[nt][0] = bp[nt * 288 + k8 * 8];
                    b[nt][1] = bp[nt * 288 + k8 * 8 + 4];
                } else {
                    b[nt][0] = bp[k8 * 8 * 136 + nt * 8];
                    b[nt][1] = bp[k8 * 8 * 136 + 544 + nt * 8];
                }
            }
#pragma unroll
            for (int mt = 0; mt < 4; mt++)
#pragma unroll
                for (int nt = 0; nt < 4; nt++) {
                    asm volatile(
                        "mma.sync.aligned.m16n8k8.row.col.f32.tf32.tf32.f32 "
                        "{%0,%1,%2,%3},{%4,%5,%6,%7},{%8,%9},{%0,%1,%2,%3};"
                        : "+f"(acc[mt][nt][0]), "+f"(acc[mt][nt][1]),
                          "+f"(acc[mt][nt][2]), "+f"(acc[mt][nt][3])
                        : "r"(a[mt][0]), "r"(a[mt][1]), "r"(a[mt][2]), "r"(a[mt][3]),
                          "r"(b[nt][0]), "r"(b[nt][1]));
                }
        }
        __syncthreads();
    }

#pragma unroll
    for (int mt = 0; mt < 4; mt++) {
        const int gr = by * GBM + wm * 64 + mt * 16 + g;
#pragma unroll
        for (int nt = 0; nt < 4; nt++) {
            const int gc = bx * GBN + wn * 32 + nt * 8 + 2 * t4;
            float b0 = bias ? bias[gc] : 0.0f;
            float b1 = bias ? bias[gc + 1] : 0.0f;
            float v0 = fmaf(alpha, acc[mt][nt][0], b0);
            float v1 = fmaf(alpha, acc[mt][nt][1], b1);
            float v2 = fmaf(alpha, acc[mt][nt][2], b0);
            float v3 = fmaf(alpha, acc[mt][nt][3], b1);
            if (roundOut) {
                v0 = to_tf32(v0); v1 = to_tf32(v1);
                v2 = to_tf32(v2); v3 = to_tf32(v3);
            }
            *(float2*)(C + (size_t)gr * ldc + gc)       = make_float2(v0, v1);
            *(float2*)(C + (size_t)(gr + 8) * ldc + gc) = make_float2(v2, v3);
        }
    }
}

// ---------------------------------------------------------------------------
// Fused flash attention: O = softmax(Q K^T / sqrt(128)) V
// QKV: [8192, 768] rows = Q(128) | K(128) | V(512), tf32-rounded.
// Grid (2, 64): blockIdx.x = V half (256 cols), blockIdx.y = Q block (128 rows).
// 256 threads, 8 warps; each warp: 16 Q rows, all keys, 256 V cols.
// ---------------------------------------------------------------------------
#define FKT 64                     // keys per tile
#define FNT (NROWS / FKT)          // 128 tiles
#define SMQ_STRIDE 132
#define SMK_STRIDE 132
#define SMV_STRIDE 264
#define SMQ_SZ (128 * SMQ_STRIDE)
#define SMK_SZ (FKT * SMK_STRIDE)
#define SMV_SZ (FKT * SMV_STRIDE)
#define FLASH_SMEM ((SMQ_SZ + 2 * SMK_SZ + SMV_SZ) * 4)

__global__ void __launch_bounds__(256, 1) flash_kernel(
    const float* __restrict__ QKV, float* __restrict__ O)
{
    extern __shared__ float sm[];
    float* smQ = sm;
    float* smK = sm + SMQ_SZ;
    float* smV = sm + SMQ_SZ + 2 * SMK_SZ;

    const int t    = threadIdx.x;
    const int w    = t >> 5;
    const int lane = t & 31;
    const int g    = lane >> 2;
    const int t4   = lane & 3;
    const int vh   = blockIdx.x;
    const int qb   = blockIdx.y;

    const float* Qg = QKV + (size_t)qb * 128 * 768;
    const float* Kg = QKV + 128;
    const float* Vg = QKV + 256 + vh * 256;

    // prologue: load Q block (128x128) and K tile 0 as one cp.async group
#pragma unroll
    for (int i = 0; i < 16; i++) {
        int idx = t + i * 256;
        int r = idx >> 5, c = (idx & 31) * 4;
        cp16(smQ + r * SMQ_STRIDE + c, Qg + (size_t)r * 768 + c);
    }
#pragma unroll
    for (int i = 0; i < 8; i++) {
        int idx = t + i * 256;
        int r = idx >> 5, c = (idx & 31) * 4;
        cp16(smK + r * SMK_STRIDE + c, Kg + (size_t)r * 768 + c);
    }
    cp_commit();

    const float alpha = 0.08838834764831845f;  // 1/sqrt(128)
    float m0 = -FLT_MAX, m1 = -FLT_MAX, l0 = 0.0f, l1 = 0.0f;
    float o[32][4];
#pragma unroll
    for (int nt = 0; nt < 32; nt++)
#pragma unroll
        for (int r = 0; r < 4; r++) o[nt][r] = 0.0f;

    const uint32_t* ap = (const uint32_t*)(smQ + (16 * w + g) * SMQ_STRIDE + t4);
    const float*    vp = smV + t4 * SMV_STRIDE + g;

    for (int kt = 0; kt < FNT; kt++) {
        cp_wait0();          // K(kt) (and everything older) complete
        __syncthreads();     // + all warps done with smV / previous K stage

        // prefetch V(kt), then K(kt+1)
        {
            const float* Vt = Vg + (size_t)kt * FKT * 768;
#pragma unroll
            for (int i = 0; i < 16; i++) {
                int idx = t + i * 256;
                int r = idx >> 6, c = (idx & 63) * 4;
                cp16(smV + r * SMV_STRIDE + c, Vt + (size_t)r * 768 + c);
            }
            cp_commit();
        }
        if (kt + 1 < FNT) {
            const float* Kt = Kg + (size_t)(kt + 1) * FKT * 768;
            float* dst = smK + ((kt + 1) & 1) * SMK_SZ;
#pragma unroll
            for (int i = 0; i < 8; i++) {
                int idx = t + i * 256;
                int r = idx >> 5, c = (idx & 31) * 4;
                cp16(dst + r * SMK_STRIDE + c, Kt + (size_t)r * 768 + c);
            }
            cp_commit();
        }

        // ---- S = Q @ K^T for this key tile (16 rows x 64 keys per warp) ----
        float s[8][4];
#pragma unroll
        for (int nt = 0; nt < 8; nt++)
#pragma unroll
            for (int r = 0; r < 4; r++) s[nt][r] = 0.0f;

        const uint32_t* bp = (const uint32_t*)(smK + (kt & 1) * SMK_SZ + g * SMK_STRIDE + t4);
#pragma unroll
        for (int k8 = 0; k8 < 16; k8++) {
            uint32_t a0 = ap[k8 * 8];
            uint32_t a1 = ap[8 * SMQ_STRIDE + k8 * 8];
            uint32_t a2 = ap[k8 * 8 + 4];
            uint32_t a3 = ap[8 * SMQ_STRIDE + k8 * 8 + 4];
#pragma unroll
            for (int nt = 0; nt < 8; nt++) {
                uint32_t b0 = bp[nt * 8 * SMK_STRIDE + k8 * 8];
                uint32_t b1 = bp[nt * 8 * SMK_STRIDE + k8 * 8 + 4];
                asm volatile(
                    "mma.sync.aligned.m16n8k8.row.col.f32.tf32.tf32.f32 "
                    "{%0,%1,%2,%3},{%4,%5,%6,%7},{%8,%9},{%0,%1,%2,%3};"
                    : "+f"(s[nt][0]), "+f"(s[nt][1]), "+f"(s[nt][2]), "+f"(s[nt][3])
                    : "r"(a0), "r"(a1), "r"(a2), "r"(a3), "r"(b0), "r"(b1));
            }
        }

        // ---- online softmax (rows g and g+8 of this warp's 16) ----
        float mx0 = -FLT_MAX, mx1 = -FLT_MAX;
#pragma unroll
        for (int nt = 0; nt < 8; nt++) {
            mx0 = fmaxf(mx0, fmaxf(s[nt][0], s[nt][1]));
            mx1 = fmaxf(mx1, fmaxf(s[nt][2], s[nt][3]));
        }
        mx0 = fmaxf(mx0, __shfl_xor_sync(0xffffffff, mx0, 1));
        mx0 = fmaxf(mx0, __shfl_xor_sync(0xffffffff, mx0, 2));
        mx1 = fmaxf(mx1, __shfl_xor_sync(0xffffffff, mx1, 1));
        mx1 = fmaxf(mx1, __shfl_xor_sync(0xffffffff, mx1, 2));
        mx0 *= alpha;  mx1 *= alpha;

        float mn0 = fmaxf(m0, mx0);
        float mn1 = fmaxf(m1, mx1);
        float f0 = __expf(m0 - mn0);
        float f1 = __expf(m1 - mn1);
        m0 = mn0;  m1 = mn1;

        float sum0 = 0.0f, sum1 = 0.0f;
#pragma unroll
        for (int nt = 0; nt < 8; nt++) {
            s[nt][0] = __expf(fmaf(alpha, s[nt][0], -m0));
            s[nt][1] = __expf(fmaf(alpha, s[nt][1], -m0));
            s[nt][2] = __expf(fmaf(alpha, s[nt][2], -m1));
            s[nt][3] = __expf(fmaf(alpha, s[nt][3], -m1));
            sum0 += s[nt][0] + s[nt][1];
            sum1 += s[nt][2] + s[nt][3];
        }
        sum0 += __shfl_xor_sync(0xffffffff, sum0, 1);
        sum0 += __shfl_xor_sync(0xffffffff, sum0, 2);
        sum1 += __shfl_xor_sync(0xffffffff, sum1, 1);
        sum1 += __shfl_xor_sync(0xffffffff, sum1, 2);
        l0 = fmaf(l0, f0, sum0);
        l1 = fmaf(l1, f1, sum1);

        // rescale O only when the running max actually moved (warp vote)
        bool nochange = (f0 == 1.0f) && (f1 == 1.0f);
        if (!__all_sync(0xffffffff, nochange)) {
#pragma unroll
            for (int nt = 0; nt < 32; nt++) {
                o[nt][0] *= f0; o[nt][1] *= f0;
                o[nt][2] *= f1; o[nt][3] *= f1;
            }
        }

        // ---- remap P: C-fragment -> A-fragment via quad shuffles, cvt tf32 ----
        uint32_t pa[8][4];
        const int base = lane & ~3;
        const int srcA = base + (t4 >> 1);
        const int srcB = srcA + 2;
        const bool oddc = (t4 & 1);
#pragma unroll
        for (int j = 0; j < 8; j++) {
            float lo, hi, v;
            lo = __shfl_sync(0xffffffff, s[j][0], srcA);
            hi = __shfl_sync(0xffffffff, s[j][1], srcA);
            v = oddc ? hi : lo; pa[j][0] = __float_as_uint(to_tf32(v));
            lo = __shfl_sync(0xffffffff, s[j][2], srcA);
            hi = __shfl_sync(0xffffffff, s[j][3], srcA);
            v = oddc ? hi : lo; pa[j][1] = __float_as_uint(to_tf32(v));
            lo = __shfl_sync(0xffffffff, s[j][0], srcB);
            hi = __shfl_sync(0xffffffff, s[j][1], srcB);
            v = oddc ? hi : lo; pa[j][2] = __float_as_uint(to_tf32(v));
            lo = __shfl_sync(0xffffffff, s[j][2], srcB);
            hi = __shfl_sync(0xffffffff, s[j][3], srcB);
            v = oddc ? hi : lo; pa[j][3] = __float_as_uint(to_tf32(v));
        }

        // V(kt) arrived?  (K(kt+1) may still be in flight)
        if (kt + 1 < FNT) cp_wait1(); else cp_wait0();
        __syncthreads();

        // ---- O += P @ V ----
#pragma unroll
        for (int k8 = 0; k8 < 8; k8++) {
            const float* vrow = vp + k8 * 8 * SMV_STRIDE;
#pragma unroll
            for (int nt = 0; nt < 32; nt++) {
                uint32_t b0 = __float_as_uint(vrow[nt * 8]);
                uint32_t b1 = __float_as_uint(vrow[4 * SMV_STRIDE + nt * 8]);
                asm volatile(
                    "mma.sync.aligned.m16n8k8.row.col.f32.tf32.tf32.f32 "
                    "{%0,%1,%2,%3},{%4,%5,%6,%7},{%8,%9},{%0,%1,%2,%3};"
                    : "+f"(o[nt][0]), "+f"(o[nt][1]), "+f"(o[nt][2]), "+f"(o[nt][3])
                    : "r"(pa[k8][0]), "r"(pa[k8][1]), "r"(pa[k8][2]), "r"(pa[k8][3]),
                      "r"(b0), "r"(b1));
            }
        }
    }

    // ---- epilogue: O /= l, tf32-round, store ----
    const float il0 = 1.0f / l0;
    const float il1 = 1.0f / l1;
    const int r0 = qb * 128 + w * 16 + g;
    const int colb = vh * 256 + 2 * t4;
#pragma unroll
    for (int nt = 0; nt < 32; nt++) {
        int gc = colb + nt * 8;
        float2 v0 = make_float2(to_tf32(o[nt][0] * il0), to_tf32(o[nt][1] * il0));
        float2 v1 = make_float2(to_tf32(o[nt][2] * il1), to_tf32(o[nt][3] * il1));
        *(float2*)(O + (size_t)r0 * DMODEL + gc)       = v0;
        *(float2*)(O + (size_t)(r0 + 8) * DMODEL + gc) = v1;
    }
}

// ---------------------------------------------------------------------------
// Weight prep kernels
// ---------------------------------------------------------------------------
__global__ void cvt_tf32_kernel(const float4* __restrict__ in, float4* __restrict__ out, int n4)
{
    int i = blockIdx.x * blockDim.x + threadIdx.x;
    if (i < n4) {
        float4 v = in[i];
        v.x = to_tf32(v.x); v.y = to_tf32(v.y);
        v.z = to_tf32(v.z); v.w = to_tf32(v.w);
        out[i] = v;
    }
}

__global__ void concat_qkv_kernel(const float* __restrict__ WQ, const float* __restrict__ WK,
                                  const float* __restrict__ WV, float* __restrict__ out)
{
    int idx = blockIdx.x * blockDim.x + threadIdx.x;   // 512*768
    if (idx >= DMODEL * 768) return;
    int r = idx / 768, c = idx % 768;
    float v;
    if (c < 128)      v = WQ[r * 128 + c];
    else if (c < 256) v = WK[r * 128 + (c - 128)];
    else              v = WV[r * 512 + (c - 256)];
    out[idx] = to_tf32(v);
}

// ---------------------------------------------------------------------------
// FF1: out = tf32(relu(LN(x @ W1 + b1)))
// ---------------------------------------------------------------------------
__global__ void __launch_bounds__(128) ff1_kernel(
    const float* __restrict__ x, const float* __restrict__ W1,
    const float* __restrict__ b1, const float* __restrict__ g1,
    const float* __restrict__ be1, float* __restrict__ out)
{
    const int row = blockIdx.x;
    const float x0 = x[row * 3 + 0];
    const float x1 = x[row * 3 + 1];
    const float x2 = x[row * 3 + 2];
    const int t = threadIdx.x;

    float v[4];
    float s = 0.0f, s2 = 0.0f;
#pragma unroll
    for (int i = 0; i < 4; i++) {
        int j = i * 128 + t;
        float val = fmaf(x0, W1[j], fmaf(x1, W1[DMODEL + j], fmaf(x2, W1[2 * DMODEL + j], b1[j])));
        v[i] = val;
        s += val;
        s2 = fmaf(val, val, s2);
    }
    s  = blockReduceSum(s);
    s2 = blockReduceSum(s2);
    const float mean = s * (1.0f / DMODEL);
    const float var  = s2 * (1.0f / DMODEL) - mean * mean;
    const float inv  = rsqrtf(var + 1e-5f);
#pragma unroll
    for (int i = 0; i < 4; i++) {
        int j = i * 128 + t;
        float y = fmaf((v[i] - mean) * inv, g1[j], be1[j]);
        out[(size_t)row * DMODEL + j] = to_tf32(fmaxf(y, 0.0f));
    }
}

// ---------------------------------------------------------------------------
// In-place LayerNorm + ReLU
// ---------------------------------------------------------------------------
__global__ void __launch_bounds__(256) ln_relu_kernel(
    float* __restrict__ X, int D,
    const float* __restrict__ g, const float* __restrict__ be, int roundOut)
{
    const int row = blockIdx.x;
    float* x = X + (size_t)row * D;
    const int t = threadIdx.x;
    const int per = D >> 8;

    float v[4];
    float s = 0.0f, s2 = 0.0f;
    for (int i = 0; i < per; i++) {
        float val = x[i * 256 + t];
        v[i] = val;
        s += val;
        s2 = fmaf(val, val, s2);
    }
    s  = blockReduceSum(s);
    s2 = blockReduceSum(s2);
    const float invD = 1.0f / (float)D;
    const float mean = s * invD;
    const float var  = s2 * invD - mean * mean;
    const float inv  = rsqrtf(var + 1e-5f);
    for (int i = 0; i < per; i++) {
        int j = i * 256 + t;
        float y = fmaxf(fmaf((v[i] - mean) * inv, g[j], be[j]), 0.0f);
        x[j] = roundOut ? to_tf32(y) : y;
    }
}

// ---------------------------------------------------------------------------
// Host side
// ---------------------------------------------------------------------------
static const int SMEM_NN = (2 * 128 * 36 + 2 * 32 * 136) * 4;
static const int SMEM_NT = (4 * 128 * 36) * 4;

static void launch_gemm_nn(int M, int N, int K,
                           const float* A, int lda, const float* B, int ldb,
                           float* C, int ldc, const float* bias, float alpha, int roundOut)
{
    dim3 grid(N / GBN, M / GBM);
    gemm_tf32<false><<<grid, 256, SMEM_NN>>>(M, N, K, A, lda, B, ldb, C, ldc, bias, alpha, roundOut);
}
static void launch_cvt(const float* in, float* out, int n)
{
    int n4 = n / 4;
    cvt_tf32_kernel<<<(n4 + 255) / 256, 256>>>((const float4*)in, (float4*)out, n4);
}

extern "C" void kernel_launch(void* const* d_in, const int* in_sizes, int n_in,
                              void* d_out, int out_size)
{
    const float* x   = (const float*)d_in[0];
    const float* W1  = (const float*)d_in[1];
    const float* b1  = (const float*)d_in[2];
    const float* g1  = (const float*)d_in[3];
    const float* be1 = (const float*)d_in[4];
    const float* W2  = (const float*)d_in[5];
    const float* b2  = (const float*)d_in[6];
    const float* g2  = (const float*)d_in[7];
    const float* be2 = (const float*)d_in[8];
    const float* WQ  = (const float*)d_in[9];
    const float* WK  = (const float*)d_in[10];
    const float* WV  = (const float*)d_in[11];
    const float* WO  = (const float*)d_in[12];
    const float* Wf  = (const float*)d_in[13];
    const float* bf  = (const float*)d_in[14];
    const float* gf  = (const float*)d_in[15];
    const float* bef = (const float*)d_in[16];
    float* out = (float*)d_out;

    cudaFuncSetAttribute(gemm_tf32<false>, cudaFuncAttributeMaxDynamicSharedMemorySize, SMEM_NN);
    cudaFuncSetAttribute(gemm_tf32<true>,  cudaFuncAttributeMaxDynamicSharedMemorySize, SMEM_NT);
    cudaFuncSetAttribute(flash_kernel, cudaFuncAttributeMaxDynamicSharedMemorySize, FLASH_SMEM);

    float *h, *tmp, *QKV, *AV, *cat, *W2r, *Wqkv, *WOr, *Wfr;
    cudaGetSymbolAddress((void**)&h,    g_h);
    cudaGetSymbolAddress((void**)&tmp,  g_tmp);
    cudaGetSymbolAddress((void**)&QKV,  g_QKV);
    cudaGetSymbolAddress((void**)&AV,   g_AV);
    cudaGetSymbolAddress((void**)&cat,  g_cat);
    cudaGetSymbolAddress((void**)&W2r,  g_W2r);
    cudaGetSymbolAddress((void**)&Wqkv, g_Wqkv);
    cudaGetSymbolAddress((void**)&WOr,  g_WOr);
    cudaGetSymbolAddress((void**)&Wfr,  g_Wfr);

    // weight prep
    launch_cvt(W2, W2r, DMODEL * DMODEL);
    launch_cvt(WO, WOr, DMODEL * DMODEL);
    launch_cvt(Wf, Wfr, 4 * DMODEL * OUTF);
    concat_qkv_kernel<<<(DMODEL * 768 + 255) / 256, 256>>>(WQ, WK, WV, Wqkv);

    // FF1 (K=3 fused) -> h (tf32)
    ff1_kernel<<<NROWS, 128>>>(x, W1, b1, g1, be1, h);

    // FF2
    launch_gemm_nn(NROWS, DMODEL, DMODEL, h, DMODEL, W2r, DMODEL, tmp, DMODEL, b2, 1.0f, 0);
    ln_relu_kernel<<<NROWS, 256>>>(tmp, DMODEL, g2, be2, 1);

    const float* cur = tmp;
    int ld_cur = DMODEL;

    for (int it = 0; it < 4; it++) {
        // fused QKV projection: [N,768] = cur @ Wqkv
        launch_gemm_nn(NROWS, 768, ld_cur == DMODEL ? DMODEL : DMODEL,  // K = 512 always
                       cur, ld_cur, Wqkv, 768, QKV, 768, nullptr, 1.0f, 1);

        // flash attention -> AV (tf32)
        flash_kernel<<<dim3(2, 64), 256, FLASH_SMEM>>>(QKV, AV);

        // a_it = AV @ WO -> cat[:, it*512:(it+1)*512]
        float* a_out = cat + it * DMODEL;
        launch_gemm_nn(NROWS, DMODEL, DMODEL, AV, DMODEL, WOr, DMODEL, a_out, 4 * DMODEL, nullptr, 1.0f, 1);

        cur = a_out;
        ld_cur = 4 * DMODEL;
    }

    // Final FF
    launch_gemm_nn(NROWS, OUTF, 4 * DMODEL, cat, 4 * DMODEL, Wfr, OUTF, out, OUTF, bf, 1.0f, 0);
    ln_relu_kernel<<<NROWS, 256>>>(out, OUTF, gf, bef, 0);
}

// round 5
// speedup vs baseline: 1.7053x; 1.7053x over previous
#include <cuda_runtime.h>
#include <cuda_fp16.h>
#include <math.h>
#include <float.h>
#include <stdint.h>

// ---------------------------------------------------------------------------
// PointEncoder: FF1 -> FF2 -> 4x attention -> concat -> FF_final
// N=8192, D=512, MD=128, OUT_F=1024.
// FP16 tensor-core GEMMs (fp32 accumulate), fp32 softmax/LN.
// ---------------------------------------------------------------------------

#define NROWS 8192
#define DMODEL 512
#define OUTF 1024

// Activations (fp16)
__device__ __half g_h[NROWS * DMODEL];
__device__ __half g_tmp[NROWS * DMODEL];
__device__ __half g_QKV[NROWS * 768];            // Q(128)|K(128)|V(512) per row
__device__ __half g_Vt[DMODEL * NROWS];          // V transposed [512][8192]
__device__ __half g_AV[NROWS * DMODEL];
__device__ __half g_cat[NROWS * 4 * DMODEL];
// Weights, transposed to [N][K], fp16
__device__ __half g_W2t[DMODEL * DMODEL];
__device__ __half g_Wqkvt[768 * DMODEL];
__device__ __half g_WOt[DMODEL * DMODEL];
__device__ __half g_Wft[OUTF * 4 * DMODEL];

__device__ __forceinline__ uint32_t pack2(float x, float y) {
    __half2 h = __floats2half2_rn(x, y);
    return *(uint32_t*)&h;
}

// ---------------------------------------------------------------------------
// Reductions
// ---------------------------------------------------------------------------
__device__ __forceinline__ float warpReduceSum(float v) {
#pragma unroll
    for (int o = 16; o > 0; o >>= 1) v += __shfl_xor_sync(0xffffffff, v, o);
    return v;
}
__device__ float blockReduceSum(float v) {
    __shared__ float sh[32];
    __shared__ float res;
    int lane = threadIdx.x & 31, wid = threadIdx.x >> 5;
    v = warpReduceSum(v);
    if (lane == 0) sh[wid] = v;
    __syncthreads();
    int nw = (blockDim.x + 31) >> 5;
    float t = (threadIdx.x < nw) ? sh[threadIdx.x] : 0.0f;
    if (wid == 0) { t = warpReduceSum(t); if (lane == 0) res = t; }
    __syncthreads();
    return res;
}

// ---------------------------------------------------------------------------
// cp.async helpers
// ---------------------------------------------------------------------------
__device__ __forceinline__ void cp16h(__half* dst, const __half* src) {
    uint32_t d = (uint32_t)__cvta_generic_to_shared(dst);
    asm volatile("cp.async.cg.shared.global [%0], [%1], 16;\n" :: "r"(d), "l"(src));
}
__device__ __forceinline__ void cp_commit() { asm volatile("cp.async.commit_group;\n"); }
__device__ __forceinline__ void cp_wait1() { asm volatile("cp.async.wait_group 1;\n"); }
__device__ __forceinline__ void cp_wait0() { asm volatile("cp.async.wait_group 0;\n"); }

#define MMA_F16(c, a0, a1, a2, a3, b0, b1)                                   \
    asm volatile(                                                            \
        "mma.sync.aligned.m16n8k16.row.col.f32.f16.f16.f32 "                 \
        "{%0,%1,%2,%3},{%4,%5,%6,%7},{%8,%9},{%0,%1,%2,%3};"                 \
        : "+f"((c)[0]), "+f"((c)[1]), "+f"((c)[2]), "+f"((c)[3])             \
        : "r"(a0), "r"(a1), "r"(a2), "r"(a3), "r"(b0), "r"(b1))

// ---------------------------------------------------------------------------
// FP16 GEMM (NT): C[M,N] = A[M,K] @ Bt[N,K]^T + bias
// A, Bt fp16 row-major; C = OutT (half or float). fp32 accumulate.
// 128x128x32 tile, 256 threads (8 warps 2x4), warp 64x32, mma m16n8k16.
// M%128==0, N%128==0, K%32==0.
// ---------------------------------------------------------------------------
#define HST 40            // smem row stride in halves (32 + 8 pad)
#define HSZ (128 * HST)   // halves per stage (A or B)

template <typename OutT>
__global__ void __launch_bounds__(256, 2) gemm_f16(
    int M, int N, int K,
    const __half* __restrict__ A, int lda,
    const __half* __restrict__ Bt, int ldb,
    OutT* __restrict__ C, int ldc,
    const float* __restrict__ bias)
{
    __shared__ __half sm[4 * HSZ];   // A0,A1,B0,B1

    const int t    = threadIdx.x;
    const int wid  = t >> 5;
    const int lane = t & 31;
    const int g    = lane >> 2;
    const int t4   = lane & 3;
    const int wm   = wid & 1;
    const int wn   = wid >> 1;
    const int bx   = blockIdx.x;
    const int by   = blockIdx.y;

    const __half* Ab = A  + (size_t)by * 128 * lda;
    const __half* Bb = Bt + (size_t)bx * 128 * ldb;

    const int lr = t >> 1;             // load row 0..127
    const int lc = (t & 1) * 16;       // load col (halves): 0 or 16

    float acc[4][4][4];
#pragma unroll
    for (int mt = 0; mt < 4; mt++)
#pragma unroll
        for (int nt = 0; nt < 4; nt++)
#pragma unroll
            for (int r = 0; r < 4; r++) acc[mt][nt][r] = 0.0f;

    const int tiles = K / 32;

    auto load_tile = [&](int stage, int k0) {
        __half* as = sm + stage * HSZ;
        __half* bs = sm + (2 + stage) * HSZ;
        cp16h(as + lr * HST + lc,     Ab + (size_t)lr * lda + k0 + lc);
        cp16h(as + lr * HST + lc + 8, Ab + (size_t)lr * lda + k0 + lc + 8);
        cp16h(bs + lr * HST + lc,     Bb + (size_t)lr * ldb + k0 + lc);
        cp16h(bs + lr * HST + lc + 8, Bb + (size_t)lr * ldb + k0 + lc + 8);
        cp_commit();
    };

    load_tile(0, 0);

    for (int tt = 0; tt < tiles; tt++) {
        if (tt + 1 < tiles) {
            load_tile((tt + 1) & 1, (tt + 1) * 32);
            cp_wait1();
        } else {
            cp_wait0();
        }
        __syncthreads();

        const int stage = tt & 1;
        const uint32_t* au = (const uint32_t*)(sm + stage * HSZ);
        const uint32_t* bu = (const uint32_t*)(sm + (2 + stage) * HSZ);
        // u32 row stride = HST/2 = 20

#pragma unroll
        for (int ks = 0; ks < 2; ks++) {
            uint32_t a[4][4];
#pragma unroll
            for (int mt = 0; mt < 4; mt++) {
                int r0 = wm * 64 + mt * 16 + g;
                a[mt][0] = au[r0 * 20 + ks * 8 + t4];
                a[mt][1] = au[(r0 + 8) * 20 + ks * 8 + t4];
                a[mt][2] = au[r0 * 20 + ks * 8 + t4 + 4];
                a[mt][3] = au[(r0 + 8) * 20 + ks * 8 + t4 + 4];
            }
            uint32_t b[4][2];
#pragma unroll
            for (int nt = 0; nt < 4; nt++) {
                int n0 = wn * 32 + nt * 8 + g;
                b[nt][0] = bu[n0 * 20 + ks * 8 + t4];
                b[nt][1] = bu[n0 * 20 + ks * 8 + t4 + 4];
            }
#pragma unroll
            for (int mt = 0; mt < 4; mt++)
#pragma unroll
                for (int nt = 0; nt < 4; nt++)
                    MMA_F16(acc[mt][nt], a[mt][0], a[mt][1], a[mt][2], a[mt][3],
                            b[nt][0], b[nt][1]);
        }
        __syncthreads();
    }

    // epilogue
#pragma unroll
    for (int mt = 0; mt < 4; mt++) {
        const int gr = by * 128 + wm * 64 + mt * 16 + g;
#pragma unroll
        for (int nt = 0; nt < 4; nt++) {
            const int gc = bx * 128 + wn * 32 + nt * 8 + 2 * t4;
            float b0 = bias ? bias[gc] : 0.0f;
            float b1 = bias ? bias[gc + 1] : 0.0f;
            float v0 = acc[mt][nt][0] + b0;
            float v1 = acc[mt][nt][1] + b1;
            float v2 = acc[mt][nt][2] + b0;
            float v3 = acc[mt][nt][3] + b1;
            if (sizeof(OutT) == 2) {
                *(uint32_t*)((__half*)C + (size_t)gr * ldc + gc)       = pack2(v0, v1);
                *(uint32_t*)((__half*)C + (size_t)(gr + 8) * ldc + gc) = pack2(v2, v3);
            } else {
                *(float2*)((float*)C + (size_t)gr * ldc + gc)       = make_float2(v0, v1);
                *(float2*)((float*)C + (size_t)(gr + 8) * ldc + gc) = make_float2(v2, v3);
            }
        }
    }
}

// ---------------------------------------------------------------------------
// Fused flash attention (fp16): O = softmax(Q K^T / sqrt(128)) V
// QKV [8192][768] fp16 (Q|K|V), Vt [512][8192] fp16.
// Grid (2, 64): x = V half (256 cols), y = Q block (128 rows). 256 threads.
// Each warp: 16 Q rows, all keys, 256 V cols.
// ---------------------------------------------------------------------------
#define FKT 64
#define FNT (NROWS / FKT)
#define QST 136                       // Q/K smem stride (halves)
#define VST 72                        // Vt smem stride (halves)
#define SMQ_SZ (128 * QST)
#define SMK_SZ (FKT * QST)
#define SMV_SZ (256 * VST)
#define FLASH_SMEM ((SMQ_SZ + 2 * SMK_SZ + SMV_SZ) * 2)

__global__ void __launch_bounds__(256, 1) flash_kernel(
    const __half* __restrict__ QKV, const __half* __restrict__ Vt,
    __half* __restrict__ O)
{
    extern __shared__ __half smh[];
    __half* smQ = smh;
    __half* smK = smh + SMQ_SZ;
    __half* smV = smh + SMQ_SZ + 2 * SMK_SZ;

    const int t    = threadIdx.x;
    const int w    = t >> 5;
    const int lane = t & 31;
    const int g    = lane >> 2;
    const int t4   = lane & 3;
    const int vh   = blockIdx.x;
    const int qb   = blockIdx.y;

    // prologue: Q block (128 rows x 128 halves) + K tile 0, one group
#pragma unroll
    for (int i = 0; i < 8; i++) {
        int idx = t + i * 256;                    // 2048 chunks
        int r = idx >> 4, c = (idx & 15) * 8;
        cp16h(smQ + r * QST + c, QKV + (size_t)(qb * 128 + r) * 768 + c);
    }
#pragma unroll
    for (int i = 0; i < 4; i++) {
        int idx = t + i * 256;                    // 1024 chunks
        int r = idx >> 4, c = (idx & 15) * 8;
        cp16h(smK + r * QST + c, QKV + (size_t)r * 768 + 128 + c);
    }
    cp_commit();

    const float alpha = 0.08838834764831845f;     // 1/sqrt(128)
    float m0 = -FLT_MAX, m1 = -FLT_MAX, l0 = 0.0f, l1 = 0.0f;
    float o[32][4];
#pragma unroll
    for (int nt = 0; nt < 32; nt++)
#pragma unroll
        for (int r = 0; r < 4; r++) o[nt][r] = 0.0f;

    const uint32_t* qu = (const uint32_t*)smQ;    // row stride 68
    const uint32_t* vu = (const uint32_t*)smV;    // row stride 36
    const int qr = w * 16 + g;

    for (int kt = 0; kt < FNT; kt++) {
        cp_wait0();
        __syncthreads();

        // prefetch V(kt) [256 cols x 64 keys from Vt], then K(kt+1)
#pragma unroll
        for (int i = 0; i < 8; i++) {
            int idx = t + i * 256;                // 2048 chunks
            int r = idx >> 3, c = (idx & 7) * 8;
            cp16h(smV + r * VST + c,
                  Vt + (size_t)(vh * 256 + r) * NROWS + kt * FKT + c);
        }
        cp_commit();
        if (kt + 1 < FNT) {
            __half* dst = smK + ((kt + 1) & 1) * SMK_SZ;
#pragma unroll
            for (int i = 0; i < 4; i++) {
                int idx = t + i * 256;
                int r = idx >> 4, c = (idx & 15) * 8;
                cp16h(dst + r * QST + c,
                      QKV + (size_t)((kt + 1) * FKT + r) * 768 + 128 + c);
            }
            cp_commit();
        }

        // ---- S = Q @ K^T (16 rows x 64 keys per warp) ----
        float s[8][4];
#pragma unroll
        for (int nt = 0; nt < 8; nt++)
#pragma unroll
            for (int r = 0; r < 4; r++) s[nt][r] = 0.0f;

        const uint32_t* ku = (const uint32_t*)(smK + (kt & 1) * SMK_SZ);
#pragma unroll
        for (int ks = 0; ks < 8; ks++) {
            uint32_t a0 = qu[qr * 68 + ks * 8 + t4];
            uint32_t a1 = qu[(qr + 8) * 68 + ks * 8 + t4];
            uint32_t a2 = qu[qr * 68 + ks * 8 + t4 + 4];
            uint32_t a3 = qu[(qr + 8) * 68 + ks * 8 + t4 + 4];
#pragma unroll
            for (int nt = 0; nt < 8; nt++) {
                int kk = nt * 8 + g;
                uint32_t b0 = ku[kk * 68 + ks * 8 + t4];
                uint32_t b1 = ku[kk * 68 + ks * 8 + t4 + 4];
                MMA_F16(s[nt], a0, a1, a2, a3, b0, b1);
            }
        }

        // ---- online softmax (rows qr and qr+8) ----
        float mx0 = -FLT_MAX, mx1 = -FLT_MAX;
#pragma unroll
        for (int nt = 0; nt < 8; nt++) {
            mx0 = fmaxf(mx0, fmaxf(s[nt][0], s[nt][1]));
            mx1 = fmaxf(mx1, fmaxf(s[nt][2], s[nt][3]));
        }
        mx0 = fmaxf(mx0, __shfl_xor_sync(0xffffffff, mx0, 1));
        mx0 = fmaxf(mx0, __shfl_xor_sync(0xffffffff, mx0, 2));
        mx1 = fmaxf(mx1, __shfl_xor_sync(0xffffffff, mx1, 1));
        mx1 = fmaxf(mx1, __shfl_xor_sync(0xffffffff, mx1, 2));
        mx0 *= alpha;  mx1 *= alpha;

        float mn0 = fmaxf(m0, mx0);
        float mn1 = fmaxf(m1, mx1);
        float f0 = __expf(m0 - mn0);
        float f1 = __expf(m1 - mn1);
        m0 = mn0;  m1 = mn1;

        float sum0 = 0.0f, sum1 = 0.0f;
#pragma unroll
        for (int nt = 0; nt < 8; nt++) {
            s[nt][0] = __expf(fmaf(alpha, s[nt][0], -m0));
            s[nt][1] = __expf(fmaf(alpha, s[nt][1], -m0));
            s[nt][2] = __expf(fmaf(alpha, s[nt][2], -m1));
            s[nt][3] = __expf(fmaf(alpha, s[nt][3], -m1));
            sum0 += s[nt][0] + s[nt][1];
            sum1 += s[nt][2] + s[nt][3];
        }
        sum0 += __shfl_xor_sync(0xffffffff, sum0, 1);
        sum0 += __shfl_xor_sync(0xffffffff, sum0, 2);
        sum1 += __shfl_xor_sync(0xffffffff, sum1, 1);
        sum1 += __shfl_xor_sync(0xffffffff, sum1, 2);
        l0 = fmaf(l0, f0, sum0);
        l1 = fmaf(l1, f1, sum1);

        bool nochange = (f0 == 1.0f) && (f1 == 1.0f);
        if (!__all_sync(0xffffffff, nochange)) {
#pragma unroll
            for (int nt = 0; nt < 32; nt++) {
                o[nt][0] *= f0; o[nt][1] *= f0;
                o[nt][2] *= f1; o[nt][3] *= f1;
            }
        }

        // ---- P (C-frag) -> fp16 A-frag: direct pack, no shuffles ----
        uint32_t pa[4][4];
#pragma unroll
        for (int j = 0; j < 4; j++) {
            pa[j][0] = pack2(s[2 * j][0], s[2 * j][1]);
            pa[j][1] = pack2(s[2 * j][2], s[2 * j][3]);
            pa[j][2] = pack2(s[2 * j + 1][0], s[2 * j + 1][1]);
            pa[j][3] = pack2(s[2 * j + 1][2], s[2 * j + 1][3]);
        }

        if (kt + 1 < FNT) cp_wait1(); else cp_wait0();
        __syncthreads();

        // ---- O += P @ V ----
#pragma unroll
        for (int j = 0; j < 4; j++) {
#pragma unroll
            for (int nt = 0; nt < 32; nt++) {
                int vc = nt * 8 + g;
                uint32_t b0 = vu[vc * 36 + j * 8 + t4];
                uint32_t b1 = vu[vc * 36 + j * 8 + t4 + 4];
                MMA_F16(o[nt], pa[j][0], pa[j][1], pa[j][2], pa[j][3], b0, b1);
            }
        }
    }

    // ---- epilogue ----
    const float il0 = 1.0f / l0;
    const float il1 = 1.0f / l1;
    const int r0 = qb * 128 + w * 16 + g;
    const int colb = vh * 256 + 2 * t4;
#pragma unroll
    for (int nt = 0; nt < 32; nt++) {
        int gc = colb + nt * 8;
        *(uint32_t*)(O + (size_t)r0 * DMODEL + gc) =
            pack2(o[nt][0] * il0, o[nt][1] * il0);
        *(uint32_t*)(O + (size_t)(r0 + 8) * DMODEL + gc) =
            pack2(o[nt][2] * il1, o[nt][3] * il1);
    }
}

// ---------------------------------------------------------------------------
// Weight transpose+cvt: in float [K][N] (ld ldin) -> out half [N][K] (ld ldout)
// K,N multiples of 32. Grid (K/32, N/32), 256 threads.
// ---------------------------------------------------------------------------
__global__ void tcvt_kernel(const float* __restrict__ in, int ldin,
                            __half* __restrict__ out, int ldout)
{
    __shared__ float sm[32][33];
    const int k0 = blockIdx.x * 32;
    const int n0 = blockIdx.y * 32;
    const int tx = threadIdx.x & 31;
    const int ty = threadIdx.x >> 5;
#pragma unroll
    for (int i = 0; i < 4; i++)
        sm[ty + 8 * i][tx] = in[(size_t)(k0 + ty + 8 * i) * ldin + n0 + tx];
    __syncthreads();
#pragma unroll
    for (int i = 0; i < 4; i++)
        out[(size_t)(n0 + ty + 8 * i) * ldout + k0 + tx] =
            __float2half_rn(sm[tx][ty + 8 * i]);
}

// ---------------------------------------------------------------------------
// V transpose (half->half): V rows of QKV [8192][768] cols 256.. -> Vt [512][8192]
// Grid (8192/32, 512/32), 256 threads.
// ---------------------------------------------------------------------------
__global__ void vtrans_kernel(const __half* __restrict__ QKV, __half* __restrict__ Vt)
{
    __shared__ __half sm[32][34];
    const int k0 = blockIdx.x * 32;   // key index
    const int n0 = blockIdx.y * 32;   // V col index
    const int tx = threadIdx.x & 31;
    const int ty = threadIdx.x >> 5;
#pragma unroll
    for (int i = 0; i < 4; i++)
        sm[ty + 8 * i][tx] = QKV[(size_t)(k0 + ty + 8 * i) * 768 + 256 + n0 + tx];
    __syncthreads();
#pragma unroll
    for (int i = 0; i < 4; i++)
        Vt[(size_t)(n0 + ty + 8 * i) * NROWS + k0 + tx] = sm[tx][ty + 8 * i];
}

// ---------------------------------------------------------------------------
// FF1: h = fp16(relu(LN(x @ W1 + b1))), x:[N,3]
// ---------------------------------------------------------------------------
__global__ void __launch_bounds__(128) ff1_kernel(
    const float* __restrict__ x, const float* __restrict__ W1,
    const float* __restrict__ b1, const float* __restrict__ g1,
    const float* __restrict__ be1, __half* __restrict__ out)
{
    const int row = blockIdx.x;
    const float x0 = x[row * 3 + 0];
    const float x1 = x[row * 3 + 1];
    const float x2 = x[row * 3 + 2];
    const int t = threadIdx.x;

    float v[4];
    float s = 0.0f, s2 = 0.0f;
#pragma unroll
    for (int i = 0; i < 4; i++) {
        int j = i * 128 + t;
        float val = fmaf(x0, W1[j], fmaf(x1, W1[DMODEL + j], fmaf(x2, W1[2 * DMODEL + j], b1[j])));
        v[i] = val;
        s += val;
        s2 = fmaf(val, val, s2);
    }
    s  = blockReduceSum(s);
    s2 = blockReduceSum(s2);
    const float mean = s * (1.0f / DMODEL);
    const float var  = s2 * (1.0f / DMODEL) - mean * mean;
    const float inv  = rsqrtf(var + 1e-5f);
#pragma unroll
    for (int i = 0; i < 4; i++) {
        int j = i * 128 + t;
        float y = fmaf((v[i] - mean) * inv, g1[j], be1[j]);
        out[(size_t)row * DMODEL + j] = __float2half_rn(fmaxf(y, 0.0f));
    }
}

// ---------------------------------------------------------------------------
// LayerNorm + ReLU, in-place. T = __half or float. D%256==0, D<=1024.
// ---------------------------------------------------------------------------
template <typename T>
__global__ void __launch_bounds__(256) ln_relu_kernel(
    T* __restrict__ X, int D, const float* __restrict__ g, const float* __restrict__ be)
{
    const int row = blockIdx.x;
    T* x = X + (size_t)row * D;
    const int t = threadIdx.x;
    const int per = D >> 8;

    float v[4];
    float s = 0.0f, s2 = 0.0f;
    for (int i = 0; i < per; i++) {
        float val = (float)x[i * 256 + t];
        v[i] = val;
        s += val;
        s2 = fmaf(val, val, s2);
    }
    s  = blockReduceSum(s);
    s2 = blockReduceSum(s2);
    const float invD = 1.0f / (float)D;
    const float mean = s * invD;
    const float var  = s2 * invD - mean * mean;
    const float inv  = rsqrtf(var + 1e-5f);
    for (int i = 0; i < per; i++) {
        int j = i * 256 + t;
        float y = fmaxf(fmaf((v[i] - mean) * inv, g[j], be[j]), 0.0f);
        x[j] = (T)y;
    }
}

// ---------------------------------------------------------------------------
// Host side
// ---------------------------------------------------------------------------
template <typename OutT>
static void launch_gemm(int M, int N, int K,
                        const __half* A, int lda, const __half* Bt, int ldb,
                        OutT* C, int ldc, const float* bias)
{
    dim3 grid(N / 128, M / 128);
    gemm_f16<OutT><<<grid, 256>>>(M, N, K, A, lda, Bt, ldb, C, ldc, bias);
}

extern "C" void kernel_launch(void* const* d_in, const int* in_sizes, int n_in,
                              void* d_out, int out_size)
{
    const float* x   = (const float*)d_in[0];
    const float* W1  = (const float*)d_in[1];
    const float* b1  = (const float*)d_in[2];
    const float* g1  = (const float*)d_in[3];
    const float* be1 = (const float*)d_in[4];
    const float* W2  = (const float*)d_in[5];
    const float* b2  = (const float*)d_in[6];
    const float* g2  = (const float*)d_in[7];
    const float* be2 = (const float*)d_in[8];
    const float* WQ  = (const float*)d_in[9];
    const float* WK  = (const float*)d_in[10];
    const float* WV  = (const float*)d_in[11];
    const float* WO  = (const float*)d_in[12];
    const float* Wf  = (const float*)d_in[13];
    const float* bf  = (const float*)d_in[14];
    const float* gf  = (const float*)d_in[15];
    const float* bef = (const float*)d_in[16];
    float* out = (float*)d_out;

    cudaFuncSetAttribute(flash_kernel, cudaFuncAttributeMaxDynamicSharedMemorySize, FLASH_SMEM);

    __half *h, *tmp, *QKV, *Vt, *AV, *cat, *W2t, *Wqkvt, *WOt, *Wft;
    cudaGetSymbolAddress((void**)&h,     g_h);
    cudaGetSymbolAddress((void**)&tmp,   g_tmp);
    cudaGetSymbolAddress((void**)&QKV,   g_QKV);
    cudaGetSymbolAddress((void**)&Vt,    g_Vt);
    cudaGetSymbolAddress((void**)&AV,    g_AV);
    cudaGetSymbolAddress((void**)&cat,   g_cat);
    cudaGetSymbolAddress((void**)&W2t,   g_W2t);
    cudaGetSymbolAddress((void**)&Wqkvt, g_Wqkvt);
    cudaGetSymbolAddress((void**)&WOt,   g_WOt);
    cudaGetSymbolAddress((void**)&Wft,   g_Wft);

    // ---- weight prep: transpose + fp16 ----
    tcvt_kernel<<<dim3(16, 16), 256>>>(W2, DMODEL, W2t, DMODEL);
    tcvt_kernel<<<dim3(16, 4),  256>>>(WQ, 128, Wqkvt, DMODEL);                 // rows 0..127
    tcvt_kernel<<<dim3(16, 4),  256>>>(WK, 128, Wqkvt + 128 * DMODEL, DMODEL);  // rows 128..255
    tcvt_kernel<<<dim3(16, 16), 256>>>(WV, DMODEL, Wqkvt + 256 * DMODEL, DMODEL);
    tcvt_kernel<<<dim3(16, 16), 256>>>(WO, DMODEL, WOt, DMODEL);
    tcvt_kernel<<<dim3(64, 32), 256>>>(Wf, OUTF, Wft, 4 * DMODEL);

    // ---- FF1 ----
    ff1_kernel<<<NROWS, 128>>>(x, W1, b1, g1, be1, h);

    // ---- FF2 ----
    launch_gemm<__half>(NROWS, DMODEL, DMODEL, h, DMODEL, W2t, DMODEL, tmp, DMODEL, b2);
    ln_relu_kernel<__half><<<NROWS, 256>>>(tmp, DMODEL, g2, be2);

    const __half* cur = tmp;
    int ld_cur = DMODEL;

    for (int it = 0; it < 4; it++) {
        // QKV projection: [N,768] = cur @ Wqkv
        launch_gemm<__half>(NROWS, 768, DMODEL, cur, ld_cur, Wqkvt, DMODEL, QKV, 768, nullptr);

        // V transpose for flash B-operands
        vtrans_kernel<<<dim3(NROWS / 32, DMODEL / 32), 256>>>(QKV, Vt);

        // flash attention
        flash_kernel<<<dim3(2, 64), 256, FLASH_SMEM>>>(QKV, Vt, AV);

        // a_it = AV @ WO -> cat[:, it*512:(it+1)*512]
        __half* a_out = cat + it * DMODEL;
        launch_gemm<__half>(NROWS, DMODEL, DMODEL, AV, DMODEL, WOt, DMODEL, a_out, 4 * DMODEL, nullptr);

        cur = a_out;
        ld_cur = 4 * DMODEL;
    }

    // ---- Final FF ----
    launch_gemm<float>(NROWS, OUTF, 4 * DMODEL, cat, 4 * DMODEL, Wft, 4 * DMODEL, out, OUTF, bf);
    ln_relu_kernel<float><<<NROWS, 256>>>(out, OUTF, gf, bef);
}